// round 6
// baseline (speedup 1.0000x reference)
#include <cuda_runtime.h>

#define FULLMASK 0xffffffffu
constexpr int Bn = 2048;
constexpr int Sn = 2048;
constexpr int K  = 20;     // taps for E-FIR / G prefix (tail ~2e-5)
constexpr int KS = 12;     // sigma-feedback taps in scan (tail ~5e-5 measured-scale)
constexpr int CCH = 16;    // time chunks per row
constexpr int LCH = 128;   // stored steps per chunk
constexpr int WUP = 63;    // warm-up steps
constexpr float LOG2E = 1.4426950408889634f;
constexpr float LN2   = 0.6931471805599453f;

// ---- static scratch ----
__device__ float g_E[(size_t)Bn * Sn + 64];   // pre-scaled by LOG2E, G folded in; padded
__device__ float g_alpha[K];
__device__ float g_beta[K];                   // pre-scaled by LOG2E
__device__ float g_gam[K + 1];                // raw prefix sums incl fcb

// ============================================================
// Kernel A: single warp, barrier-free.
// p distributed 2/lane; broadcast via shfl; W columns in registers.
// alpha_k = p_k·u, beta_k = p_k·v, gamma prefix; p_{k+1} = A^T p_k.
// ============================================================
__global__ void __launch_bounds__(32) coef_kernel(
        const float* __restrict__ Wih, const float* __restrict__ Bih,
        const float* __restrict__ Whh, const float* __restrict__ Bhh,
        const float* __restrict__ Fcw, const float* __restrict__ Fcb) {
    const int l = threadIdx.x;
    float W0[64], W1[64];                 // W0[r] = Whh[r][l], W1[r] = Whh[r][l+32]
    #pragma unroll
    for (int r = 0; r < 64; ++r) {
        W0[r] = Whh[r * 64 + l];
        W1[r] = Whh[r * 64 + l + 32];
    }
    const float u0 = Wih[2 * l],            v0 = Wih[2 * l + 1];
    const float u1 = Wih[2 * (l + 32)],     v1 = Wih[2 * (l + 32) + 1];
    const float b0 = Bih[l] + Bhh[l];
    const float b1 = Bih[l + 32] + Bhh[l + 32];
    float p0 = Fcw[l], p1 = Fcw[l + 32];
    float gacc = Fcb[0];
    if (l == 0) g_gam[0] = gacc;

    #pragma unroll 1
    for (int k = 0; k < K; ++k) {
        // dots with current p
        float da = fmaf(p0, u0, p1 * u1);
        float db = fmaf(p0, v0, p1 * v1);
        float dc = fmaf(p0, b0, p1 * b1);
        #pragma unroll
        for (int o = 16; o; o >>= 1) {
            da += __shfl_xor_sync(FULLMASK, da, o);
            db += __shfl_xor_sync(FULLMASK, db, o);
            dc += __shfl_xor_sync(FULLMASK, dc, o);
        }
        gacc += dc;                        // uniform across lanes
        if (l == 0) {
            g_alpha[k]   = da;
            g_beta[k]    = db * LOG2E;
            g_gam[k + 1] = gacc;
        }
        if (k == K - 1) break;
        // p <- A^T p  (np_j = sum_r W[r][j] p[r])
        float n0a = 0.f, n0b = 0.f, n1a = 0.f, n1b = 0.f;
        #pragma unroll
        for (int r = 0; r < 32; ++r) {
            float plo = __shfl_sync(FULLMASK, p0, r);
            float phi = __shfl_sync(FULLMASK, p1, r);
            n0a = fmaf(W0[r],      plo, n0a);
            n0b = fmaf(W0[r + 32], phi, n0b);
            n1a = fmaf(W1[r],      plo, n1a);
            n1b = fmaf(W1[r + 32], phi, n1b);
        }
        p0 = n0a + n0b;
        p1 = n1a + n1b;
    }
}

// ============================================================
// Kernel B: variance -> out[b][0];  g_E[b][i] = (FIR_alpha(res^2)[i]
//           + G[min(i+1,K)]) * LOG2E
// ============================================================
__global__ void __launch_bounds__(256) fir_kernel(const float* __restrict__ res,
                                                  float* __restrict__ out) {
    __shared__ __align__(16) float xs[31 + Sn + 9];
    __shared__ float sal[K];
    __shared__ float sgam[K + 1];
    __shared__ float rsum[8], rsq[8];
    const int b  = blockIdx.x;
    const int td = threadIdx.x;
    const float* r = res + (size_t)b * Sn;

    if (td < 31)     xs[td] = 0.f;
    if (td < K)      sal[td] = g_alpha[td];
    if (td < K + 1)  sgam[td] = g_gam[td];
    if (td < 9)      xs[31 + Sn + td] = 0.f;

    float sum = 0.f, sq = 0.f;
    #pragma unroll
    for (int i = td; i < Sn / 4; i += 256) {
        float4 q = reinterpret_cast<const float4*>(r)[i];
        xs[31 + 4 * i + 0] = q.x * q.x;
        xs[31 + 4 * i + 1] = q.y * q.y;
        xs[31 + 4 * i + 2] = q.z * q.z;
        xs[31 + 4 * i + 3] = q.w * q.w;
        sum += (q.x + q.y) + (q.z + q.w);
        sq = fmaf(q.x, q.x, sq); sq = fmaf(q.y, q.y, sq);
        sq = fmaf(q.z, q.z, sq); sq = fmaf(q.w, q.w, sq);
    }
    #pragma unroll
    for (int o = 16; o; o >>= 1) {
        sum += __shfl_xor_sync(FULLMASK, sum, o);
        sq  += __shfl_xor_sync(FULLMASK, sq, o);
    }
    if ((td & 31) == 0) { rsum[td >> 5] = sum; rsq[td >> 5] = sq; }
    __syncthreads();
    if (td == 0) {
        float S = 0.f, Q = 0.f;
        #pragma unroll
        for (int w = 0; w < 8; ++w) { S += rsum[w]; Q += rsq[w]; }
        out[(size_t)b * Sn] = (Q - S * S * (1.f / Sn)) * (1.f / (Sn - 1));
    }

    const int i0 = td * 8;
    float w[40];
    #pragma unroll
    for (int m = 0; m < 10; ++m)
        reinterpret_cast<float4*>(w)[m] = *reinterpret_cast<const float4*>(&xs[i0 + 4 * m]);
    float acc[8] = {0.f, 0.f, 0.f, 0.f, 0.f, 0.f, 0.f, 0.f};
    #pragma unroll
    for (int k = 0; k < K; ++k) {
        float a = sal[k];
        #pragma unroll
        for (int i = 0; i < 8; ++i) acc[i] = fmaf(a, w[i + 31 - k], acc[i]);
    }
    #pragma unroll
    for (int i = 0; i < 8; ++i) {
        int t = i0 + i + 1;
        acc[i] = (acc[i] + sgam[min(t, K)]) * LOG2E;
    }
    float* eo = g_E + (size_t)b * Sn + i0;
    reinterpret_cast<float4*>(eo)[0] = make_float4(acc[0], acc[1], acc[2], acc[3]);
    reinterpret_cast<float4*>(eo)[1] = make_float4(acc[4], acc[5], acc[6], acc[7]);
}

// ============================================================
// Kernel C: chunk-parallel scan. 16 chunks/row x 2048 rows = 32768 threads.
// Chunk c>0 starts at t=128c-63 with zero history (contractive warm-up),
// stores t in [128c, 128c+128). Chunk 0 starts exactly at t=1.
// Ring of 16 sigmas in registers, compile-time slots.
// ============================================================
__global__ void __launch_bounds__(128) scan_kernel(float* __restrict__ out) {
    const int gid = blockIdx.x * 128 + threadIdx.x;
    const int b = gid & (Bn - 1);
    const int c = gid >> 11;               // 0..15

    float beta[KS];
    #pragma unroll
    for (int k = 0; k < KS; ++k) beta[k] = g_beta[k];   // pre-scaled by LOG2E

    const float* Erow = g_E + (size_t)b * Sn;
    float* orow = out + (size_t)b * Sn;

    const int t_start = (c == 0) ? 1 : (c * LCH - WUP);   // === 1 (mod 16)
    const int nb = (c == 0) ? 8 : 12;
    const int qlo = (c == 0) ? 0 : c * LCH;               // first stored index
    const int qhi = c * LCH + LCH;                        // one-past-end

    float hist[16];
    #pragma unroll
    for (int i = 0; i < 16; ++i) hist[i] = 0.f;
    float sigma = 0.f;
    float q0 = 0.f, q1 = 0.f, q2 = 0.f, q3 = 0.f;
    if (c == 0) { sigma = orow[0]; hist[0] = sigma; q0 = sigma; }

    float4 ea, eb4, ec, ed;
    {
        const float4* ep = reinterpret_cast<const float4*>(Erow + (t_start - 1));
        ea = ep[0]; eb4 = ep[1]; ec = ep[2]; ed = ep[3];
    }

    #pragma unroll 1
    for (int blk = 0; blk < nb; ++blk) {
        const int tb = t_start + 16 * blk;
        const float4* epn = reinterpret_cast<const float4*>(Erow + (tb + 15));
        float4 na = epn[0], nb4_ = epn[1], nc = epn[2], nd = epn[3];  // pad covers OOB
        float ecur[16] = {ea.x, ea.y, ea.z, ea.w, eb4.x, eb4.y, eb4.z, eb4.w,
                          ec.x, ec.y, ec.z, ec.w, ed.x, ed.y, ed.z, ed.w};
        #pragma unroll
        for (int ss = 0; ss < 16; ++ss) {
            const int t = tb + ss;                   // t === 1+ss (mod 16)
            float p0 = 0.f, p1 = 0.f, p2 = 0.f, p3 = ecur[ss];
            #pragma unroll
            for (int k = 1; k < KS; k += 4) p0 = fmaf(beta[k], hist[(ss - k) & 15], p0);
            #pragma unroll
            for (int k = 2; k < KS; k += 4) p1 = fmaf(beta[k], hist[(ss - k) & 15], p1);
            #pragma unroll
            for (int k = 3; k < KS; k += 4) p2 = fmaf(beta[k], hist[(ss - k) & 15], p2);
            #pragma unroll
            for (int k = 4; k < KS; k += 4) p3 = fmaf(beta[k], hist[(ss - k) & 15], p3);
            float rest = (p0 + p1) + (p2 + p3);
            float y = fmaf(beta[0], sigma, rest);    // y = x * log2(e)
            float e;
            asm("ex2.approx.f32 %0, %1;" : "=f"(e) : "f"(y));
            float lg;
            asm("lg2.approx.f32 %0, %1;" : "=f"(lg) : "f"(e + 1.0f));
            sigma = fmaf(lg, LN2, 1e-6f);            // softplus(x) + EPS
            hist[(1 + ss) & 15] = sigma;
            const int tm4 = (1 + ss) & 3;            // compile-time
            if (tm4 == 0)      q0 = sigma;
            else if (tm4 == 1) q1 = sigma;
            else if (tm4 == 2) q2 = sigma;
            else {
                q3 = sigma;
                if (t - 3 >= qlo && t < qhi)
                    *reinterpret_cast<float4*>(orow + (t - 3)) =
                        make_float4(q0, q1, q2, q3);
            }
        }
        ea = na; eb4 = nb4_; ec = nc; ed = nd;
    }
}

extern "C" void kernel_launch(void* const* d_in, const int* in_sizes, int n_in,
                              void* d_out, int out_size) {
    (void)in_sizes; (void)n_in; (void)out_size;
    const float* res = (const float*)d_in[0];
    const float* Wih = (const float*)d_in[1];
    const float* Bih = (const float*)d_in[2];
    const float* Whh = (const float*)d_in[3];
    const float* Bhh = (const float*)d_in[4];
    const float* Fcw = (const float*)d_in[5];
    const float* Fcb = (const float*)d_in[6];
    float* out = (float*)d_out;

    coef_kernel<<<1, 32>>>(Wih, Bih, Whh, Bhh, Fcw, Fcb);
    fir_kernel<<<Bn, 256>>>(res, out);
    scan_kernel<<<(Bn * CCH) / 128, 128>>>(out);
}

// round 7
// speedup vs baseline: 1.0571x; 1.0571x over previous
#include <cuda_runtime.h>

#define FULLMASK 0xffffffffu
constexpr int Bn = 2048;
constexpr int Sn = 2048;
constexpr int K  = 20;     // taps for E-FIR / G prefix
constexpr int KS = 12;     // sigma-feedback taps in scan
constexpr int CCH = 16;    // time chunks per row
constexpr int LCH = 128;   // stored steps per chunk
constexpr int WUP = 63;    // warm-up steps
constexpr float LOG2E = 1.4426950408889634f;
constexpr float LN2   = 0.6931471805599453f;

// ---- static scratch ----
__device__ float g_E[(size_t)Bn * Sn + 64];   // pre-scaled by LOG2E, G folded in; padded
__device__ float g_alpha[K];
__device__ float g_beta[K];                   // pre-scaled by LOG2E
__device__ float g_gam[K + 1];                // raw prefix sums incl fcb

// ============================================================
// Kernel A: 128 threads. W in registers (32/thread), p broadcast via smem.
// Per iter: 8x LDS.128 + 32 FMA + one 2-way smem reduce + 2 barriers.
// Dots computed once at the end from the stored P history.
// ============================================================
__global__ void __launch_bounds__(128) coef_kernel(
        const float* __restrict__ Wih, const float* __restrict__ Bih,
        const float* __restrict__ Whh, const float* __restrict__ Bhh,
        const float* __restrict__ Fcw, const float* __restrict__ Fcb) {
    __shared__ __align__(16) float P[K][64];    // p_k history
    __shared__ __align__(16) float pcur[64];
    __shared__ float red[128];
    __shared__ float uvb[3][64];
    __shared__ float sg[K];
    const int td = threadIdx.x;
    const int j  = td & 63;          // column
    const int h  = td >> 6;          // row half: rows 32h..32h+31

    float Wreg[32];                  // Wreg[r] = Whh[32h+r][j]
    #pragma unroll
    for (int r = 0; r < 32; ++r) Wreg[r] = Whh[(32 * h + r) * 64 + j];

    if (h == 0) {
        uvb[0][j] = Wih[2 * j];
        uvb[1][j] = Wih[2 * j + 1];
        uvb[2][j] = Bih[j] + Bhh[j];
        float f = Fcw[j];
        P[0][j] = f;
        pcur[j] = f;
    }
    __syncthreads();

    #pragma unroll 1
    for (int k = 1; k < K; ++k) {
        const float4* pp = reinterpret_cast<const float4*>(pcur) + 8 * h;
        float a0 = 0.f, a1 = 0.f, a2 = 0.f, a3 = 0.f;
        #pragma unroll
        for (int m = 0; m < 8; ++m) {
            float4 q = pp[m];                    // broadcast LDS.128
            a0 = fmaf(Wreg[4 * m + 0], q.x, a0);
            a1 = fmaf(Wreg[4 * m + 1], q.y, a1);
            a2 = fmaf(Wreg[4 * m + 2], q.z, a2);
            a3 = fmaf(Wreg[4 * m + 3], q.w, a3);
        }
        red[td] = (a0 + a1) + (a2 + a3);
        __syncthreads();
        if (h == 0) {
            float np = red[j] + red[64 + j];
            P[k][j] = np;
            pcur[j] = np;
        }
        __syncthreads();
    }

    if (td < K) {                    // one k per thread: 3 dots of length 64
        const float* Pk = P[td];
        float A = 0.f, B = 0.f, C = 0.f;
        #pragma unroll 8
        for (int m = 0; m < 64; ++m) {
            int jj = (m + td) & 63;  // skew: conflict-free
            float p = Pk[jj];
            A = fmaf(p, uvb[0][jj], A);
            B = fmaf(p, uvb[1][jj], B);
            C = fmaf(p, uvb[2][jj], C);
        }
        g_alpha[td] = A;
        g_beta[td]  = B * LOG2E;
        sg[td] = C;
    }
    __syncthreads();
    if (td == 0) {
        float acc = Fcb[0];
        g_gam[0] = acc;
        #pragma unroll 1
        for (int k = 0; k < K; ++k) { acc += sg[k]; g_gam[k + 1] = acc; }
    }
}

// ============================================================
// Kernel B: variance -> out[b][0];  g_E[b][i] = (FIR_alpha(res^2)[i]
//           + G[min(i+1,K)]) * LOG2E
// ============================================================
__global__ void __launch_bounds__(256) fir_kernel(const float* __restrict__ res,
                                                  float* __restrict__ out) {
    __shared__ __align__(16) float xs[31 + Sn + 9];
    __shared__ float sal[K];
    __shared__ float sgam[K + 1];
    __shared__ float rsum[8], rsq[8];
    const int b  = blockIdx.x;
    const int td = threadIdx.x;
    const float* r = res + (size_t)b * Sn;

    if (td < 31)     xs[td] = 0.f;
    if (td < K)      sal[td] = g_alpha[td];
    if (td < K + 1)  sgam[td] = g_gam[td];
    if (td < 9)      xs[31 + Sn + td] = 0.f;

    float sum = 0.f, sq = 0.f;
    #pragma unroll
    for (int i = td; i < Sn / 4; i += 256) {
        float4 q = reinterpret_cast<const float4*>(r)[i];
        xs[31 + 4 * i + 0] = q.x * q.x;
        xs[31 + 4 * i + 1] = q.y * q.y;
        xs[31 + 4 * i + 2] = q.z * q.z;
        xs[31 + 4 * i + 3] = q.w * q.w;
        sum += (q.x + q.y) + (q.z + q.w);
        sq = fmaf(q.x, q.x, sq); sq = fmaf(q.y, q.y, sq);
        sq = fmaf(q.z, q.z, sq); sq = fmaf(q.w, q.w, sq);
    }
    #pragma unroll
    for (int o = 16; o; o >>= 1) {
        sum += __shfl_xor_sync(FULLMASK, sum, o);
        sq  += __shfl_xor_sync(FULLMASK, sq, o);
    }
    if ((td & 31) == 0) { rsum[td >> 5] = sum; rsq[td >> 5] = sq; }
    __syncthreads();
    if (td == 0) {
        float S = 0.f, Q = 0.f;
        #pragma unroll
        for (int w = 0; w < 8; ++w) { S += rsum[w]; Q += rsq[w]; }
        out[(size_t)b * Sn] = (Q - S * S * (1.f / Sn)) * (1.f / (Sn - 1));
    }

    const int i0 = td * 8;
    float w[40];
    #pragma unroll
    for (int m = 0; m < 10; ++m)
        reinterpret_cast<float4*>(w)[m] = *reinterpret_cast<const float4*>(&xs[i0 + 4 * m]);
    float acc[8] = {0.f, 0.f, 0.f, 0.f, 0.f, 0.f, 0.f, 0.f};
    #pragma unroll
    for (int k = 0; k < K; ++k) {
        float a = sal[k];
        #pragma unroll
        for (int i = 0; i < 8; ++i) acc[i] = fmaf(a, w[i + 31 - k], acc[i]);
    }
    #pragma unroll
    for (int i = 0; i < 8; ++i) {
        int t = i0 + i + 1;
        acc[i] = (acc[i] + sgam[min(t, K)]) * LOG2E;
    }
    float* eo = g_E + (size_t)b * Sn + i0;
    reinterpret_cast<float4*>(eo)[0] = make_float4(acc[0], acc[1], acc[2], acc[3]);
    reinterpret_cast<float4*>(eo)[1] = make_float4(acc[4], acc[5], acc[6], acc[7]);
}

// ============================================================
// Kernel C: chunk-parallel scan. 16 chunks/row x 2048 rows = 32768 threads.
// Chunk c>0 starts at t=128c-63 with zero history (contractive warm-up),
// stores t in [128c, 128c+128). Chunk 0 starts exactly at t=1.
// ============================================================
__global__ void __launch_bounds__(128) scan_kernel(float* __restrict__ out) {
    const int gid = blockIdx.x * 128 + threadIdx.x;
    const int b = gid & (Bn - 1);
    const int c = gid >> 11;               // 0..15

    float beta[KS];
    #pragma unroll
    for (int k = 0; k < KS; ++k) beta[k] = g_beta[k];   // pre-scaled by LOG2E

    const float* Erow = g_E + (size_t)b * Sn;
    float* orow = out + (size_t)b * Sn;

    const int t_start = (c == 0) ? 1 : (c * LCH - WUP);   // === 1 (mod 16)
    const int nb = (c == 0) ? 8 : 12;
    const int qlo = (c == 0) ? 0 : c * LCH;
    const int qhi = c * LCH + LCH;

    float hist[16];
    #pragma unroll
    for (int i = 0; i < 16; ++i) hist[i] = 0.f;
    float sigma = 0.f;
    float q0 = 0.f, q1 = 0.f, q2 = 0.f, q3 = 0.f;
    if (c == 0) { sigma = orow[0]; hist[0] = sigma; q0 = sigma; }

    float4 ea, eb4, ec, ed;
    {
        const float4* ep = reinterpret_cast<const float4*>(Erow + (t_start - 1));
        ea = ep[0]; eb4 = ep[1]; ec = ep[2]; ed = ep[3];
    }

    #pragma unroll 1
    for (int blk = 0; blk < nb; ++blk) {
        const int tb = t_start + 16 * blk;
        const float4* epn = reinterpret_cast<const float4*>(Erow + (tb + 15));
        float4 na = epn[0], nb4_ = epn[1], nc = epn[2], nd = epn[3];  // pad covers OOB
        float ecur[16] = {ea.x, ea.y, ea.z, ea.w, eb4.x, eb4.y, eb4.z, eb4.w,
                          ec.x, ec.y, ec.z, ec.w, ed.x, ed.y, ed.z, ed.w};
        #pragma unroll
        for (int ss = 0; ss < 16; ++ss) {
            const int t = tb + ss;                   // t === 1+ss (mod 16)
            float p0 = 0.f, p1 = 0.f, p2 = 0.f, p3 = ecur[ss];
            #pragma unroll
            for (int k = 1; k < KS; k += 4) p0 = fmaf(beta[k], hist[(ss - k) & 15], p0);
            #pragma unroll
            for (int k = 2; k < KS; k += 4) p1 = fmaf(beta[k], hist[(ss - k) & 15], p1);
            #pragma unroll
            for (int k = 3; k < KS; k += 4) p2 = fmaf(beta[k], hist[(ss - k) & 15], p2);
            #pragma unroll
            for (int k = 4; k < KS; k += 4) p3 = fmaf(beta[k], hist[(ss - k) & 15], p3);
            float rest = (p0 + p1) + (p2 + p3);
            float y = fmaf(beta[0], sigma, rest);    // y = x * log2(e)
            float e;
            asm("ex2.approx.f32 %0, %1;" : "=f"(e) : "f"(y));
            float lg;
            asm("lg2.approx.f32 %0, %1;" : "=f"(lg) : "f"(e + 1.0f));
            sigma = fmaf(lg, LN2, 1e-6f);            // softplus(x) + EPS
            hist[(1 + ss) & 15] = sigma;
            const int tm4 = (1 + ss) & 3;            // compile-time
            if (tm4 == 0)      q0 = sigma;
            else if (tm4 == 1) q1 = sigma;
            else if (tm4 == 2) q2 = sigma;
            else {
                q3 = sigma;
                if (t - 3 >= qlo && t < qhi)
                    *reinterpret_cast<float4*>(orow + (t - 3)) =
                        make_float4(q0, q1, q2, q3);
            }
        }
        ea = na; eb4 = nb4_; ec = nc; ed = nd;
    }
}

extern "C" void kernel_launch(void* const* d_in, const int* in_sizes, int n_in,
                              void* d_out, int out_size) {
    (void)in_sizes; (void)n_in; (void)out_size;
    const float* res = (const float*)d_in[0];
    const float* Wih = (const float*)d_in[1];
    const float* Bih = (const float*)d_in[2];
    const float* Whh = (const float*)d_in[3];
    const float* Bhh = (const float*)d_in[4];
    const float* Fcw = (const float*)d_in[5];
    const float* Fcb = (const float*)d_in[6];
    float* out = (float*)d_out;

    coef_kernel<<<1, 128>>>(Wih, Bih, Whh, Bhh, Fcw, Fcb);
    fir_kernel<<<Bn, 256>>>(res, out);
    scan_kernel<<<(Bn * CCH) / 128, 128>>>(out);
}